// round 1
// baseline (speedup 1.0000x reference)
#include <cuda_runtime.h>
#include <cuda_bf16.h>

// ---------------------------------------------------------------------------
// FrameAveraging: center/covariance -> 3x3 eigh (LAPACK ssyevd emulation for
// exact sign/order match with jnp.linalg.eigh on CPU) -> 8-way sign-flipped
// frame projection.
//
// Outputs (concatenated in d_out): h [B*8,N,3], F_ops [B,8,3,3], center [B,3]
// ---------------------------------------------------------------------------

#define FA_MAXB 1024
__device__ float g_center[FA_MAXB * 3];
__device__ float g_C[FA_MAXB * 6];     // a11,a21,a31,a22,a32,a33
__device__ float g_V[FA_MAXB * 9];     // V[i][j] row-major (column j = eigvec j)

// ----------------------------- LAPACK helpers ------------------------------

__device__ __forceinline__ float f_sign(float a, float b) {
    float aa = fabsf(a);
    return (b >= 0.0f) ? aa : -aa;
}

__device__ __forceinline__ float slapy2f(float x, float y) {
    float ax = fabsf(x), ay = fabsf(y);
    float w = fmaxf(ax, ay), z = fminf(ax, ay);
    if (z == 0.0f) return w;
    float r = z / w;
    return w * sqrtf(1.0f + r * r);
}

// LAPACK >= 3.10 slartg convention: c >= 0, r = sign(f)*hypot, s = g/r.
__device__ __forceinline__ void slartgf(float f, float g, float& c, float& s, float& r) {
    if (g == 0.0f) {
        c = 1.0f; s = 0.0f; r = f;
    } else if (f == 0.0f) {
        c = 0.0f; s = (g >= 0.0f) ? 1.0f : -1.0f; r = fabsf(g);
    } else {
        float d = sqrtf(f * f + g * g);
        c = fabsf(f) / d;
        r = (f >= 0.0f) ? d : -d;
        s = g / r;
    }
}

__device__ void slaev2f(float a, float b, float c,
                        float& rt1, float& rt2, float& cs1, float& sn1) {
    float sm = a + c;
    float df = a - c;
    float adf = fabsf(df);
    float tb = b + b;
    float ab = fabsf(tb);
    float acmx, acmn;
    if (fabsf(a) > fabsf(c)) { acmx = a; acmn = c; } else { acmx = c; acmn = a; }
    float rt;
    if (adf > ab)      { float q = ab / adf;  rt = adf * sqrtf(1.0f + q * q); }
    else if (adf < ab) { float q = adf / ab;  rt = ab  * sqrtf(1.0f + q * q); }
    else               {                      rt = ab  * sqrtf(2.0f); }
    int sgn1;
    if (sm < 0.0f) {
        rt1 = 0.5f * (sm - rt); sgn1 = -1;
        rt2 = (acmx / rt1) * acmn - (b / rt1) * b;
    } else if (sm > 0.0f) {
        rt1 = 0.5f * (sm + rt); sgn1 = 1;
        rt2 = (acmx / rt1) * acmn - (b / rt1) * b;
    } else {
        rt1 = 0.5f * rt; rt2 = -0.5f * rt; sgn1 = 1;
    }
    float cs; int sgn2;
    if (df >= 0.0f) { cs = df + rt; sgn2 = 1; } else { cs = df - rt; sgn2 = -1; }
    float acs = fabsf(cs);
    if (acs > ab) {
        float ct = -tb / cs;
        sn1 = 1.0f / sqrtf(1.0f + ct * ct);
        cs1 = ct * sn1;
    } else {
        if (ab == 0.0f) { cs1 = 1.0f; sn1 = 0.0f; }
        else {
            float tn = -cs / tb;
            cs1 = 1.0f / sqrtf(1.0f + tn * tn);
            sn1 = tn * cs1;
        }
    }
    if (sgn1 == sgn2) { float tn = cs1; cs1 = -sn1; sn1 = tn; }
}

// ssteqr, COMPZ='I', n=3. d[3], e[2], z initialized to identity by the caller.
__device__ void ssteqr3(float d[3], float e[2], float z[3][3]) {
    const float eps = 5.9604645e-08f;          // slamch('E') for f32 = 2^-24
    const float eps2 = eps * eps;
    const float safmin = 1.1754943508222875e-38f;
    const int n = 3;
    const int nmaxit = n * 30;
    int jtot = 0;
    int l1 = 0;

    while (true) {
        if (l1 > n - 1) break;
        if (l1 > 0) e[l1 - 1] = 0.0f;
        int m = n - 1;
        for (int mm = l1; mm <= n - 2; mm++) {
            float tst = fabsf(e[mm]);
            if (tst == 0.0f) { m = mm; break; }
            if (tst <= (sqrtf(fabsf(d[mm])) * sqrtf(fabsf(d[mm + 1]))) * eps) {
                e[mm] = 0.0f; m = mm; break;
            }
        }
        int l = l1, lsv = l, lend = m, lendsv = lend;
        l1 = m + 1;
        if (lend == l) continue;
        if (fabsf(d[lend]) < fabsf(d[l])) { l = lendsv; lend = lsv; }

        if (lend > l) {
            // ---- QL iteration ----
            bool blockdone = false;
            while (!blockdone) {
                int m2 = lend;
                if (l != lend) {
                    for (int mm = l; mm <= lend - 1; mm++) {
                        float tst = e[mm] * e[mm];
                        if (tst <= (eps2 * fabsf(d[mm])) * fabsf(d[mm + 1]) + safmin) {
                            m2 = mm; break;
                        }
                    }
                }
                if (m2 < lend) e[m2] = 0.0f;
                float p = d[l];
                if (m2 == l) {
                    d[l] = p; l++;
                    if (l <= lend) continue;
                    blockdone = true; continue;
                }
                if (m2 == l + 1) {
                    float rt1, rt2, c, s;
                    slaev2f(d[l], e[l], d[l + 1], rt1, rt2, c, s);
                    for (int i = 0; i < 3; i++) {
                        float temp = z[i][l + 1];
                        z[i][l + 1] = c * temp - s * z[i][l];
                        z[i][l]     = s * temp + c * z[i][l];
                    }
                    d[l] = rt1; d[l + 1] = rt2; e[l] = 0.0f;
                    l += 2;
                    if (l <= lend) continue;
                    blockdone = true; continue;
                }
                if (jtot == nmaxit) { blockdone = true; continue; }
                jtot++;
                float g = (d[l + 1] - p) / (2.0f * e[l]);
                float r = slapy2f(g, 1.0f);
                g = d[m2] - p + e[l] / (g + f_sign(r, g));
                float s = 1.0f, c = 1.0f;
                p = 0.0f;
                float csv[2], snv[2];
                for (int i = m2 - 1; i >= l; i--) {
                    float f = s * e[i];
                    float b2 = c * e[i];
                    slartgf(g, f, c, s, r);
                    if (i != m2 - 1) e[i + 1] = r;
                    g = d[i + 1] - p;
                    r = (d[i] - g) * s + 2.0f * c * b2;
                    p = s * r;
                    d[i + 1] = g + p;
                    g = c * r - b2;
                    csv[i] = c; snv[i] = -s;
                }
                for (int j = m2 - 1; j >= l; j--) {        // slasr 'R','V','B'
                    float cj = csv[j], sj = snv[j];
                    for (int i = 0; i < 3; i++) {
                        float temp = z[i][j + 1];
                        z[i][j + 1] = cj * temp - sj * z[i][j];
                        z[i][j]     = sj * temp + cj * z[i][j];
                    }
                }
                d[l] = d[l] - p;
                e[l] = g;
            }
        } else {
            // ---- QR iteration ----
            bool blockdone = false;
            while (!blockdone) {
                int m2 = lend;
                if (l != lend) {
                    for (int mm = l; mm >= lend + 1; mm--) {
                        float tst = e[mm - 1] * e[mm - 1];
                        if (tst <= (eps2 * fabsf(d[mm])) * fabsf(d[mm - 1]) + safmin) {
                            m2 = mm; break;
                        }
                    }
                }
                if (m2 > lend) e[m2 - 1] = 0.0f;
                float p = d[l];
                if (m2 == l) {
                    d[l] = p; l--;
                    if (l >= lend) continue;
                    blockdone = true; continue;
                }
                if (m2 == l - 1) {
                    float rt1, rt2, c, s;
                    slaev2f(d[l - 1], e[l - 1], d[l], rt1, rt2, c, s);
                    for (int i = 0; i < 3; i++) {
                        float temp = z[i][l];
                        z[i][l]     = c * temp - s * z[i][l - 1];
                        z[i][l - 1] = s * temp + c * z[i][l - 1];
                    }
                    d[l - 1] = rt1; d[l] = rt2; e[l - 1] = 0.0f;
                    l -= 2;
                    if (l >= lend) continue;
                    blockdone = true; continue;
                }
                if (jtot == nmaxit) { blockdone = true; continue; }
                jtot++;
                float g = (d[l - 1] - p) / (2.0f * e[l - 1]);
                float r = slapy2f(g, 1.0f);
                g = d[m2] - p + e[l - 1] / (g + f_sign(r, g));
                float s = 1.0f, c = 1.0f;
                p = 0.0f;
                float csv[2], snv[2];
                for (int i = m2; i <= l - 1; i++) {
                    float f = s * e[i];
                    float b2 = c * e[i];
                    slartgf(g, f, c, s, r);
                    if (i != m2) e[i - 1] = r;
                    g = d[i] - p;
                    r = (d[i + 1] - g) * s + 2.0f * c * b2;
                    p = s * r;
                    d[i] = g + p;
                    g = c * r - b2;
                    csv[i] = c; snv[i] = s;
                }
                for (int j = m2; j <= l - 1; j++) {        // slasr 'R','V','F'
                    float cj = csv[j], sj = snv[j];
                    for (int i = 0; i < 3; i++) {
                        float temp = z[i][j + 1];
                        z[i][j + 1] = cj * temp - sj * z[i][j];
                        z[i][j]     = sj * temp + cj * z[i][j];
                    }
                }
                d[l] = d[l] - p;
                e[l - 1] = g;
            }
        }
    }
    // Selection sort ascending, swapping eigenvector columns (LAPACK label 160).
    for (int ii = 1; ii < n; ii++) {
        int i = ii - 1, k = i;
        float p = d[i];
        for (int j = ii; j < n; j++) if (d[j] < p) { k = j; p = d[j]; }
        if (k != i) {
            d[k] = d[i]; d[i] = p;
            for (int r2 = 0; r2 < 3; r2++) {
                float t = z[r2][i]; z[r2][i] = z[r2][k]; z[r2][k] = t;
            }
        }
    }
}

// ----------------------------- Kernel 1: reduce ----------------------------

__device__ __forceinline__ double warpRedD(double v) {
#pragma unroll
    for (int o = 16; o > 0; o >>= 1) v += __shfl_down_sync(0xffffffffu, v, o);
    return v;
}

__global__ void fa_reduce_kernel(const float* __restrict__ X,
                                 const float* __restrict__ mask, int N) {
    int b = blockIdx.x;
    const float4* Xb = reinterpret_cast<const float4*>(X + (size_t)b * N * 3);
    const float4* Mb = reinterpret_cast<const float4*>(mask + (size_t)b * N);

    double acc[11];
#pragma unroll
    for (int k = 0; k < 11; k++) acc[k] = 0.0;
    // acc: 0 sm, 1 sm2, 2..4 s1xyz, 5 xx, 6 xy, 7 xz, 8 yy, 9 yz, 10 zz

    int tid = threadIdx.x;
    int nq = N >> 2;
    for (int q = tid; q < nq; q += blockDim.x) {
        float4 m4 = Mb[q];
        float4 fa = Xb[q * 3 + 0];
        float4 fb = Xb[q * 3 + 1];
        float4 fc = Xb[q * 3 + 2];
        float px[4] = {fa.x, fa.w, fb.z, fc.y};
        float py[4] = {fa.y, fb.x, fb.w, fc.z};
        float pz[4] = {fa.z, fb.y, fc.x, fc.w};
        float mm[4] = {m4.x, m4.y, m4.z, m4.w};
#pragma unroll
        for (int k = 0; k < 4; k++) {
            double x = px[k], y = py[k], z = pz[k], m = mm[k];
            acc[0] += m;     acc[1] += m * m;
            acc[2] += m * x; acc[3] += m * y; acc[4] += m * z;
            acc[5] += x * x; acc[6] += x * y; acc[7] += x * z;
            acc[8] += y * y; acc[9] += y * z; acc[10] += z * z;
        }
    }

    __shared__ double sred[8][11];
    int lane = tid & 31, w = tid >> 5;
#pragma unroll
    for (int k = 0; k < 11; k++) {
        double v = warpRedD(acc[k]);
        if (lane == 0) sred[w][k] = v;
    }
    __syncthreads();
    if (tid == 0) {
        double t[11];
        int nw = blockDim.x >> 5;
#pragma unroll
        for (int k = 0; k < 11; k++) {
            double v = 0.0;
            for (int ww = 0; ww < nw; ww++) v += sred[ww][k];
            t[k] = v;
        }
        double sm = t[0], sm2 = t[1];
        double s1x = t[2], s1y = t[3], s1z = t[4];
        // f32 center exactly as reference computes (f32 divide)
        float cfx = (float)s1x / (float)sm;
        float cfy = (float)s1y / (float)sm;
        float cfz = (float)s1z / (float)sm;
        g_center[b * 3 + 0] = cfx;
        g_center[b * 3 + 1] = cfy;
        g_center[b * 3 + 2] = cfz;
        // covariance via double-precision expansion:
        // C_ij = Sxx_ij - c_i*S1_j - c_j*S1_i + c_i*c_j*Sm2
        double cx = s1x / sm, cy = s1y / sm, cz = s1z / sm;
        double Cxx = t[5]  - 2.0 * cx * s1x + cx * cx * sm2;
        double Cxy = t[6]  - cx * s1y - cy * s1x + cx * cy * sm2;
        double Cxz = t[7]  - cx * s1z - cz * s1x + cx * cz * sm2;
        double Cyy = t[8]  - 2.0 * cy * s1y + cy * cy * sm2;
        double Cyz = t[9]  - cy * s1z - cz * s1y + cy * cz * sm2;
        double Czz = t[10] - 2.0 * cz * s1z + cz * cz * sm2;
        g_C[b * 6 + 0] = (float)Cxx;   // a11
        g_C[b * 6 + 1] = (float)Cxy;   // a21
        g_C[b * 6 + 2] = (float)Cxz;   // a31
        g_C[b * 6 + 3] = (float)Cyy;   // a22
        g_C[b * 6 + 4] = (float)Cyz;   // a32
        g_C[b * 6 + 5] = (float)Czz;   // a33
    }
}

// ------------------------- Kernel 2: eigh + F_ops ---------------------------

__global__ void fa_eig_kernel(float* __restrict__ outF, float* __restrict__ outC, int B) {
    int b = blockIdx.x * blockDim.x + threadIdx.x;
    if (b >= B) return;
    float a11 = g_C[b * 6 + 0], a21 = g_C[b * 6 + 1], a31 = g_C[b * 6 + 2];
    float a22 = g_C[b * 6 + 3], a32 = g_C[b * 6 + 4], a33 = g_C[b * 6 + 5];

    // ---- ssytd2 (lower, n=3): one Householder reflector ----
    float d[3], e[2];
    float tau = 0.0f, v2 = 0.0f;
    {
        float alpha = a21;
        float xnorm = fabsf(a31);
        if (xnorm == 0.0f) {
            tau = 0.0f; v2 = 0.0f;
            e[0] = alpha;
            d[0] = a11; d[1] = a22; d[2] = a33;
            e[1] = a32;
        } else {
            float beta = -f_sign(slapy2f(alpha, xnorm), alpha);
            tau = (beta - alpha) / beta;
            v2 = a31 * (1.0f / (alpha - beta));
            e[0] = beta;
            float w1 = tau * (a22 + a32 * v2);
            float w2 = tau * (a32 + a33 * v2);
            float alpha2 = -0.5f * tau * (w1 + w2 * v2);
            w1 += alpha2;
            w2 += alpha2 * v2;
            d[0] = a11;
            d[1] = a22 - 2.0f * w1;
            e[1] = a32 - (v2 * w1 + w2);
            d[2] = a33 - 2.0f * v2 * w2;
        }
    }

    float z[3][3] = {{1.f, 0.f, 0.f}, {0.f, 1.f, 0.f}, {0.f, 0.f, 1.f}};
    ssteqr3(d, e, z);

    // ---- sormtr: V = H1 * Z, H1 = I - tau*u*u^T, u = (0, 1, v2) ----
    float V[3][3];
#pragma unroll
    for (int j = 0; j < 3; j++) {
        float t = tau * (z[1][j] + v2 * z[2][j]);
        V[0][j] = z[0][j];
        V[1][j] = z[1][j] - t;
        V[2][j] = z[2][j] - v2 * t;
    }
#pragma unroll
    for (int i = 0; i < 3; i++)
#pragma unroll
        for (int j = 0; j < 3; j++)
            g_V[b * 9 + i * 3 + j] = V[i][j];

    // F_ops[b,o,i,j] = OPS[o][j] * V[i][j]; OPS[o] = (o&4?+1:-1, o&2?+1:-1, o&1?+1:-1)
    for (int o = 0; o < 8; o++) {
        float sg[3] = {(o & 4) ? 1.f : -1.f, (o & 2) ? 1.f : -1.f, (o & 1) ? 1.f : -1.f};
#pragma unroll
        for (int i = 0; i < 3; i++)
#pragma unroll
            for (int j = 0; j < 3; j++)
                outF[(((size_t)b * 8 + o) * 3 + i) * 3 + j] = sg[j] * V[i][j];
    }
    outC[b * 3 + 0] = g_center[b * 3 + 0];
    outC[b * 3 + 1] = g_center[b * 3 + 1];
    outC[b * 3 + 2] = g_center[b * 3 + 2];
}

// ------------------------- Kernel 3: projection (h) -------------------------

__global__ void fa_project_kernel(const float* __restrict__ X,
                                  const float* __restrict__ mask,
                                  float* __restrict__ outh, int N) {
    int b = blockIdx.y;
    __shared__ float sV[9];
    __shared__ float sc[3];
    if (threadIdx.x < 9) sV[threadIdx.x] = g_V[b * 9 + threadIdx.x];
    if (threadIdx.x < 3) sc[threadIdx.x] = g_center[b * 3 + threadIdx.x];
    __syncthreads();

    int t = blockIdx.x * blockDim.x + threadIdx.x;
    int p0 = t * 4;
    if (p0 >= N) return;

    const float4* Xb = reinterpret_cast<const float4*>(X + (size_t)b * N * 3);
    const float4* Mb = reinterpret_cast<const float4*>(mask + (size_t)b * N);
    float4 fa = Xb[t * 3 + 0];
    float4 fb = Xb[t * 3 + 1];
    float4 fc = Xb[t * 3 + 2];
    float4 m4 = Mb[t];

    float cx = sc[0], cy = sc[1], cz = sc[2];
    float v0 = sV[0], v1 = sV[1], v2 = sV[2];
    float v3 = sV[3], v4 = sV[4], v5 = sV[5];
    float v6 = sV[6], v7 = sV[7], v8 = sV[8];

    float px[4] = {fa.x, fa.w, fb.z, fc.y};
    float py[4] = {fa.y, fb.x, fb.w, fc.z};
    float pz[4] = {fa.z, fb.y, fc.x, fc.w};
    float mm[4] = {m4.x, m4.y, m4.z, m4.w};

    float yv[12];
#pragma unroll
    for (int k = 0; k < 4; k++) {
        float xcx = px[k] - cx * mm[k];
        float xcy = py[k] - cy * mm[k];
        float xcz = pz[k] - cz * mm[k];
        // y_i = sum_j V[j][i] * xc_j  (projection onto eigenvector i)
        yv[k * 3 + 0] = v0 * xcx + v3 * xcy + v6 * xcz;
        yv[k * 3 + 1] = v1 * xcx + v4 * xcy + v7 * xcz;
        yv[k * 3 + 2] = v2 * xcx + v5 * xcy + v8 * xcz;
    }

    float* ob = outh + ((size_t)b * 8) * N * 3 + (size_t)p0 * 3;
    size_t ostride = (size_t)N * 3;
#pragma unroll
    for (int o = 0; o < 8; o++) {
        float s0 = (o & 4) ? 1.f : -1.f;
        float s1 = (o & 2) ? 1.f : -1.f;
        float s2 = (o & 1) ? 1.f : -1.f;
        float4 w0 = make_float4(s0 * yv[0], s1 * yv[1], s2 * yv[2],  s0 * yv[3]);
        float4 w1 = make_float4(s1 * yv[4], s2 * yv[5], s0 * yv[6],  s1 * yv[7]);
        float4 w2 = make_float4(s2 * yv[8], s0 * yv[9], s1 * yv[10], s2 * yv[11]);
        float4* op = reinterpret_cast<float4*>(ob + (size_t)o * ostride);
        __stcs(op + 0, w0);
        __stcs(op + 1, w1);
        __stcs(op + 2, w2);
    }
}

// ------------------------------- launch ------------------------------------

extern "C" void kernel_launch(void* const* d_in, const int* in_sizes, int n_in,
                              void* d_out, int out_size) {
    const float* X = (const float*)d_in[0];
    const float* mask = (const float*)d_in[1];
    float* out = (float*)d_out;

    long long BN = in_sizes[1];                       // B*N
    long long B = ((long long)out_size - 24LL * BN) / 75LL;
    if (B < 1) B = 1;
    int N = (int)(BN / B);

    float* outF = out + 24LL * BN;                    // F_ops after h
    float* outC = outF + 72LL * B;                    // center after F_ops

    fa_reduce_kernel<<<(int)B, 256>>>(X, mask, N);
    fa_eig_kernel<<<(int)((B + 31) / 32), 32>>>(outF, outC, (int)B);
    dim3 grid((N / 4 + 255) / 256, (unsigned)B);
    fa_project_kernel<<<grid, 256>>>(X, mask, out, N);
}

// round 2
// speedup vs baseline: 1.2534x; 1.2534x over previous
#include <cuda_runtime.h>
#include <cuda_bf16.h>

// ---------------------------------------------------------------------------
// FrameAveraging: center/covariance -> 3x3 eigh (LAPACK ssyevd emulation for
// exact sign/order match with jnp.linalg.eigh) -> 8-way sign-flipped
// frame projection.
//
// Outputs (concatenated in d_out): h [B*8,N,3], F_ops [B,8,3,3], center [B,3]
//
// R2 changes vs R1:
//  - reduce: fp32 per-thread accumulation (was fp64 -> fp64-pipe-bound),
//    4 CTAs per batch, one fp64 atomicAdd per block into g_acc.
//  - eig: one matrix per CTA (lane 0 only) to kill warp divergence in the
//    branchy ssteqr emulation. Finalize (center/C from g_acc) moved here.
//    g_acc is re-zeroed here after use so every launch leaves it zeroed
//    (zero-initialized at module load; deterministic across graph replays).
// ---------------------------------------------------------------------------

#define FA_MAXB 1024
__device__ double g_acc[FA_MAXB * 11];   // zero-initialized; restored to 0 each launch
__device__ float g_center[FA_MAXB * 3];
__device__ float g_V[FA_MAXB * 9];       // V[i][j] row-major (column j = eigvec j)

// ----------------------------- LAPACK helpers ------------------------------

__device__ __forceinline__ float f_sign(float a, float b) {
    float aa = fabsf(a);
    return (b >= 0.0f) ? aa : -aa;
}

__device__ __forceinline__ float slapy2f(float x, float y) {
    float ax = fabsf(x), ay = fabsf(y);
    float w = fmaxf(ax, ay), z = fminf(ax, ay);
    if (z == 0.0f) return w;
    float r = z / w;
    return w * sqrtf(1.0f + r * r);
}

// LAPACK >= 3.10 slartg convention: c >= 0, r = sign(f)*hypot, s = g/r.
__device__ __forceinline__ void slartgf(float f, float g, float& c, float& s, float& r) {
    if (g == 0.0f) {
        c = 1.0f; s = 0.0f; r = f;
    } else if (f == 0.0f) {
        c = 0.0f; s = (g >= 0.0f) ? 1.0f : -1.0f; r = fabsf(g);
    } else {
        float d = sqrtf(f * f + g * g);
        c = fabsf(f) / d;
        r = (f >= 0.0f) ? d : -d;
        s = g / r;
    }
}

__device__ void slaev2f(float a, float b, float c,
                        float& rt1, float& rt2, float& cs1, float& sn1) {
    float sm = a + c;
    float df = a - c;
    float adf = fabsf(df);
    float tb = b + b;
    float ab = fabsf(tb);
    float acmx, acmn;
    if (fabsf(a) > fabsf(c)) { acmx = a; acmn = c; } else { acmx = c; acmn = a; }
    float rt;
    if (adf > ab)      { float q = ab / adf;  rt = adf * sqrtf(1.0f + q * q); }
    else if (adf < ab) { float q = adf / ab;  rt = ab  * sqrtf(1.0f + q * q); }
    else               {                      rt = ab  * sqrtf(2.0f); }
    int sgn1;
    if (sm < 0.0f) {
        rt1 = 0.5f * (sm - rt); sgn1 = -1;
        rt2 = (acmx / rt1) * acmn - (b / rt1) * b;
    } else if (sm > 0.0f) {
        rt1 = 0.5f * (sm + rt); sgn1 = 1;
        rt2 = (acmx / rt1) * acmn - (b / rt1) * b;
    } else {
        rt1 = 0.5f * rt; rt2 = -0.5f * rt; sgn1 = 1;
    }
    float cs; int sgn2;
    if (df >= 0.0f) { cs = df + rt; sgn2 = 1; } else { cs = df - rt; sgn2 = -1; }
    float acs = fabsf(cs);
    if (acs > ab) {
        float ct = -tb / cs;
        sn1 = 1.0f / sqrtf(1.0f + ct * ct);
        cs1 = ct * sn1;
    } else {
        if (ab == 0.0f) { cs1 = 1.0f; sn1 = 0.0f; }
        else {
            float tn = -cs / tb;
            cs1 = 1.0f / sqrtf(1.0f + tn * tn);
            sn1 = tn * cs1;
        }
    }
    if (sgn1 == sgn2) { float tn = cs1; cs1 = -sn1; sn1 = tn; }
}

// ssteqr, COMPZ='I', n=3. d[3], e[2], z initialized to identity by the caller.
__device__ void ssteqr3(float d[3], float e[2], float z[3][3]) {
    const float eps = 5.9604645e-08f;          // slamch('E') for f32 = 2^-24
    const float eps2 = eps * eps;
    const float safmin = 1.1754943508222875e-38f;
    const int n = 3;
    const int nmaxit = n * 30;
    int jtot = 0;
    int l1 = 0;

    while (true) {
        if (l1 > n - 1) break;
        if (l1 > 0) e[l1 - 1] = 0.0f;
        int m = n - 1;
        for (int mm = l1; mm <= n - 2; mm++) {
            float tst = fabsf(e[mm]);
            if (tst == 0.0f) { m = mm; break; }
            if (tst <= (sqrtf(fabsf(d[mm])) * sqrtf(fabsf(d[mm + 1]))) * eps) {
                e[mm] = 0.0f; m = mm; break;
            }
        }
        int l = l1, lsv = l, lend = m, lendsv = lend;
        l1 = m + 1;
        if (lend == l) continue;
        if (fabsf(d[lend]) < fabsf(d[l])) { l = lendsv; lend = lsv; }

        if (lend > l) {
            // ---- QL iteration ----
            bool blockdone = false;
            while (!blockdone) {
                int m2 = lend;
                if (l != lend) {
                    for (int mm = l; mm <= lend - 1; mm++) {
                        float tst = e[mm] * e[mm];
                        if (tst <= (eps2 * fabsf(d[mm])) * fabsf(d[mm + 1]) + safmin) {
                            m2 = mm; break;
                        }
                    }
                }
                if (m2 < lend) e[m2] = 0.0f;
                float p = d[l];
                if (m2 == l) {
                    d[l] = p; l++;
                    if (l <= lend) continue;
                    blockdone = true; continue;
                }
                if (m2 == l + 1) {
                    float rt1, rt2, c, s;
                    slaev2f(d[l], e[l], d[l + 1], rt1, rt2, c, s);
                    for (int i = 0; i < 3; i++) {
                        float temp = z[i][l + 1];
                        z[i][l + 1] = c * temp - s * z[i][l];
                        z[i][l]     = s * temp + c * z[i][l];
                    }
                    d[l] = rt1; d[l + 1] = rt2; e[l] = 0.0f;
                    l += 2;
                    if (l <= lend) continue;
                    blockdone = true; continue;
                }
                if (jtot == nmaxit) { blockdone = true; continue; }
                jtot++;
                float g = (d[l + 1] - p) / (2.0f * e[l]);
                float r = slapy2f(g, 1.0f);
                g = d[m2] - p + e[l] / (g + f_sign(r, g));
                float s = 1.0f, c = 1.0f;
                p = 0.0f;
                float csv[2], snv[2];
                for (int i = m2 - 1; i >= l; i--) {
                    float f = s * e[i];
                    float b2 = c * e[i];
                    slartgf(g, f, c, s, r);
                    if (i != m2 - 1) e[i + 1] = r;
                    g = d[i + 1] - p;
                    r = (d[i] - g) * s + 2.0f * c * b2;
                    p = s * r;
                    d[i + 1] = g + p;
                    g = c * r - b2;
                    csv[i] = c; snv[i] = -s;
                }
                for (int j = m2 - 1; j >= l; j--) {        // slasr 'R','V','B'
                    float cj = csv[j], sj = snv[j];
                    for (int i = 0; i < 3; i++) {
                        float temp = z[i][j + 1];
                        z[i][j + 1] = cj * temp - sj * z[i][j];
                        z[i][j]     = sj * temp + cj * z[i][j];
                    }
                }
                d[l] = d[l] - p;
                e[l] = g;
            }
        } else {
            // ---- QR iteration ----
            bool blockdone = false;
            while (!blockdone) {
                int m2 = lend;
                if (l != lend) {
                    for (int mm = l; mm >= lend + 1; mm--) {
                        float tst = e[mm - 1] * e[mm - 1];
                        if (tst <= (eps2 * fabsf(d[mm])) * fabsf(d[mm - 1]) + safmin) {
                            m2 = mm; break;
                        }
                    }
                }
                if (m2 > lend) e[m2 - 1] = 0.0f;
                float p = d[l];
                if (m2 == l) {
                    d[l] = p; l--;
                    if (l >= lend) continue;
                    blockdone = true; continue;
                }
                if (m2 == l - 1) {
                    float rt1, rt2, c, s;
                    slaev2f(d[l - 1], e[l - 1], d[l], rt1, rt2, c, s);
                    for (int i = 0; i < 3; i++) {
                        float temp = z[i][l];
                        z[i][l]     = c * temp - s * z[i][l - 1];
                        z[i][l - 1] = s * temp + c * z[i][l - 1];
                    }
                    d[l - 1] = rt1; d[l] = rt2; e[l - 1] = 0.0f;
                    l -= 2;
                    if (l >= lend) continue;
                    blockdone = true; continue;
                }
                if (jtot == nmaxit) { blockdone = true; continue; }
                jtot++;
                float g = (d[l - 1] - p) / (2.0f * e[l - 1]);
                float r = slapy2f(g, 1.0f);
                g = d[m2] - p + e[l - 1] / (g + f_sign(r, g));
                float s = 1.0f, c = 1.0f;
                p = 0.0f;
                float csv[2], snv[2];
                for (int i = m2; i <= l - 1; i++) {
                    float f = s * e[i];
                    float b2 = c * e[i];
                    slartgf(g, f, c, s, r);
                    if (i != m2) e[i - 1] = r;
                    g = d[i] - p;
                    r = (d[i + 1] - g) * s + 2.0f * c * b2;
                    p = s * r;
                    d[i] = g + p;
                    g = c * r - b2;
                    csv[i] = c; snv[i] = s;
                }
                for (int j = m2; j <= l - 1; j++) {        // slasr 'R','V','F'
                    float cj = csv[j], sj = snv[j];
                    for (int i = 0; i < 3; i++) {
                        float temp = z[i][j + 1];
                        z[i][j + 1] = cj * temp - sj * z[i][j];
                        z[i][j]     = sj * temp + cj * z[i][j];
                    }
                }
                d[l] = d[l] - p;
                e[l - 1] = g;
            }
        }
    }
    // Selection sort ascending, swapping eigenvector columns (LAPACK label 160).
    for (int ii = 1; ii < n; ii++) {
        int i = ii - 1, k = i;
        float p = d[i];
        for (int j = ii; j < n; j++) if (d[j] < p) { k = j; p = d[j]; }
        if (k != i) {
            d[k] = d[i]; d[i] = p;
            for (int r2 = 0; r2 < 3; r2++) {
                float t = z[r2][i]; z[r2][i] = z[r2][k]; z[r2][k] = t;
            }
        }
    }
}

// ----------------------------- Kernel 1: reduce ----------------------------
// grid (S, B), block 256. fp32 per-thread accumulation, fp64 atomic per block.

__device__ __forceinline__ float warpRedF(float v) {
#pragma unroll
    for (int o = 16; o > 0; o >>= 1) v += __shfl_down_sync(0xffffffffu, v, o);
    return v;
}

__global__ void fa_reduce_kernel(const float* __restrict__ X,
                                 const float* __restrict__ mask, int N) {
    int b = blockIdx.y;
    const float4* Xb = reinterpret_cast<const float4*>(X + (size_t)b * N * 3);
    const float4* Mb = reinterpret_cast<const float4*>(mask + (size_t)b * N);

    float acc[11];
#pragma unroll
    for (int k = 0; k < 11; k++) acc[k] = 0.0f;
    // acc: 0 sm, 1 sm2, 2..4 s1xyz, 5 xx, 6 xy, 7 xz, 8 yy, 9 yz, 10 zz

    int nq = N >> 2;
    int stride = gridDim.x * blockDim.x;
    for (int q = blockIdx.x * blockDim.x + threadIdx.x; q < nq; q += stride) {
        float4 m4 = Mb[q];
        float4 fa = Xb[q * 3 + 0];
        float4 fb = Xb[q * 3 + 1];
        float4 fc = Xb[q * 3 + 2];
        float px[4] = {fa.x, fa.w, fb.z, fc.y};
        float py[4] = {fa.y, fb.x, fb.w, fc.z};
        float pz[4] = {fa.z, fb.y, fc.x, fc.w};
        float mm[4] = {m4.x, m4.y, m4.z, m4.w};
#pragma unroll
        for (int k = 0; k < 4; k++) {
            float x = px[k], y = py[k], z = pz[k], m = mm[k];
            acc[0] += m;         acc[1] = fmaf(m, m, acc[1]);
            acc[2] = fmaf(m, x, acc[2]);
            acc[3] = fmaf(m, y, acc[3]);
            acc[4] = fmaf(m, z, acc[4]);
            acc[5] = fmaf(x, x, acc[5]);
            acc[6] = fmaf(x, y, acc[6]);
            acc[7] = fmaf(x, z, acc[7]);
            acc[8] = fmaf(y, y, acc[8]);
            acc[9] = fmaf(y, z, acc[9]);
            acc[10] = fmaf(z, z, acc[10]);
        }
    }

    __shared__ float sred[8][11];
    int lane = threadIdx.x & 31, w = threadIdx.x >> 5;
#pragma unroll
    for (int k = 0; k < 11; k++) {
        float v = warpRedF(acc[k]);
        if (lane == 0) sred[w][k] = v;
    }
    __syncthreads();
    if (threadIdx.x < 11) {
        int nw = blockDim.x >> 5;
        double v = 0.0;
        for (int ww = 0; ww < nw; ww++) v += (double)sred[ww][threadIdx.x];
        atomicAdd(&g_acc[b * 11 + threadIdx.x], v);
    }
}

// ------------------- Kernel 2: finalize + eigh + F_ops ----------------------
// One matrix per CTA (lane 0 only) -> no warp divergence in ssteqr emulation.

__global__ void fa_eig_kernel(float* __restrict__ outF, float* __restrict__ outC, int B) {
    int b = blockIdx.x;
    if (threadIdx.x != 0 || b >= B) return;

    double t[11];
#pragma unroll
    for (int k = 0; k < 11; k++) {
        t[k] = g_acc[b * 11 + k];
        g_acc[b * 11 + k] = 0.0;      // restore zero state for next launch
    }
    double sm = t[0], sm2 = t[1];
    double s1x = t[2], s1y = t[3], s1z = t[4];
    // f32 center exactly as reference computes (f32 divide)
    float cfx = (float)s1x / (float)sm;
    float cfy = (float)s1y / (float)sm;
    float cfz = (float)s1z / (float)sm;
    g_center[b * 3 + 0] = cfx;
    g_center[b * 3 + 1] = cfy;
    g_center[b * 3 + 2] = cfz;
    // C_ij = Sxx_ij - c_i*S1_j - c_j*S1_i + c_i*c_j*Sm2 (double expansion)
    double cx = s1x / sm, cy = s1y / sm, cz = s1z / sm;
    float a11 = (float)(t[5]  - 2.0 * cx * s1x + cx * cx * sm2);
    float a21 = (float)(t[6]  - cx * s1y - cy * s1x + cx * cy * sm2);
    float a31 = (float)(t[7]  - cx * s1z - cz * s1x + cx * cz * sm2);
    float a22 = (float)(t[8]  - 2.0 * cy * s1y + cy * cy * sm2);
    float a32 = (float)(t[9]  - cy * s1z - cz * s1y + cy * cz * sm2);
    float a33 = (float)(t[10] - 2.0 * cz * s1z + cz * cz * sm2);

    // ---- ssytd2 (lower, n=3): one Householder reflector ----
    float d[3], e[2];
    float tau = 0.0f, v2 = 0.0f;
    {
        float alpha = a21;
        float xnorm = fabsf(a31);
        if (xnorm == 0.0f) {
            tau = 0.0f; v2 = 0.0f;
            e[0] = alpha;
            d[0] = a11; d[1] = a22; d[2] = a33;
            e[1] = a32;
        } else {
            float beta = -f_sign(slapy2f(alpha, xnorm), alpha);
            tau = (beta - alpha) / beta;
            v2 = a31 * (1.0f / (alpha - beta));
            e[0] = beta;
            float w1 = tau * (a22 + a32 * v2);
            float w2 = tau * (a32 + a33 * v2);
            float alpha2 = -0.5f * tau * (w1 + w2 * v2);
            w1 += alpha2;
            w2 += alpha2 * v2;
            d[0] = a11;
            d[1] = a22 - 2.0f * w1;
            e[1] = a32 - (v2 * w1 + w2);
            d[2] = a33 - 2.0f * v2 * w2;
        }
    }

    float z[3][3] = {{1.f, 0.f, 0.f}, {0.f, 1.f, 0.f}, {0.f, 0.f, 1.f}};
    ssteqr3(d, e, z);

    // ---- sormtr: V = H1 * Z, H1 = I - tau*u*u^T, u = (0, 1, v2) ----
    float V[3][3];
#pragma unroll
    for (int j = 0; j < 3; j++) {
        float tt = tau * (z[1][j] + v2 * z[2][j]);
        V[0][j] = z[0][j];
        V[1][j] = z[1][j] - tt;
        V[2][j] = z[2][j] - v2 * tt;
    }
#pragma unroll
    for (int i = 0; i < 3; i++)
#pragma unroll
        for (int j = 0; j < 3; j++)
            g_V[b * 9 + i * 3 + j] = V[i][j];

    // F_ops[b,o,i,j] = OPS[o][j] * V[i][j]; OPS[o] = (o&4?+1:-1, o&2?+1:-1, o&1?+1:-1)
    for (int o = 0; o < 8; o++) {
        float sg[3] = {(o & 4) ? 1.f : -1.f, (o & 2) ? 1.f : -1.f, (o & 1) ? 1.f : -1.f};
#pragma unroll
        for (int i = 0; i < 3; i++)
#pragma unroll
            for (int j = 0; j < 3; j++)
                outF[(((size_t)b * 8 + o) * 3 + i) * 3 + j] = sg[j] * V[i][j];
    }
    outC[b * 3 + 0] = cfx;
    outC[b * 3 + 1] = cfy;
    outC[b * 3 + 2] = cfz;
}

// ------------------------- Kernel 3: projection (h) -------------------------

__global__ void fa_project_kernel(const float* __restrict__ X,
                                  const float* __restrict__ mask,
                                  float* __restrict__ outh, int N) {
    int b = blockIdx.y;
    __shared__ float sV[9];
    __shared__ float sc[3];
    if (threadIdx.x < 9) sV[threadIdx.x] = g_V[b * 9 + threadIdx.x];
    if (threadIdx.x < 3) sc[threadIdx.x] = g_center[b * 3 + threadIdx.x];
    __syncthreads();

    int t = blockIdx.x * blockDim.x + threadIdx.x;
    int p0 = t * 4;
    if (p0 >= N) return;

    const float4* Xb = reinterpret_cast<const float4*>(X + (size_t)b * N * 3);
    const float4* Mb = reinterpret_cast<const float4*>(mask + (size_t)b * N);
    float4 fa = Xb[t * 3 + 0];
    float4 fb = Xb[t * 3 + 1];
    float4 fc = Xb[t * 3 + 2];
    float4 m4 = Mb[t];

    float cx = sc[0], cy = sc[1], cz = sc[2];
    float v0 = sV[0], v1 = sV[1], v2 = sV[2];
    float v3 = sV[3], v4 = sV[4], v5 = sV[5];
    float v6 = sV[6], v7 = sV[7], v8 = sV[8];

    float px[4] = {fa.x, fa.w, fb.z, fc.y};
    float py[4] = {fa.y, fb.x, fb.w, fc.z};
    float pz[4] = {fa.z, fb.y, fc.x, fc.w};
    float mm[4] = {m4.x, m4.y, m4.z, m4.w};

    float yv[12];
#pragma unroll
    for (int k = 0; k < 4; k++) {
        float xcx = px[k] - cx * mm[k];
        float xcy = py[k] - cy * mm[k];
        float xcz = pz[k] - cz * mm[k];
        // y_i = sum_j V[j][i] * xc_j  (projection onto eigenvector i)
        yv[k * 3 + 0] = v0 * xcx + v3 * xcy + v6 * xcz;
        yv[k * 3 + 1] = v1 * xcx + v4 * xcy + v7 * xcz;
        yv[k * 3 + 2] = v2 * xcx + v5 * xcy + v8 * xcz;
    }

    float* ob = outh + ((size_t)b * 8) * N * 3 + (size_t)p0 * 3;
    size_t ostride = (size_t)N * 3;
#pragma unroll
    for (int o = 0; o < 8; o++) {
        float s0 = (o & 4) ? 1.f : -1.f;
        float s1 = (o & 2) ? 1.f : -1.f;
        float s2 = (o & 1) ? 1.f : -1.f;
        float4 w0 = make_float4(s0 * yv[0], s1 * yv[1], s2 * yv[2],  s0 * yv[3]);
        float4 w1 = make_float4(s1 * yv[4], s2 * yv[5], s0 * yv[6],  s1 * yv[7]);
        float4 w2 = make_float4(s2 * yv[8], s0 * yv[9], s1 * yv[10], s2 * yv[11]);
        float4* op = reinterpret_cast<float4*>(ob + (size_t)o * ostride);
        __stcs(op + 0, w0);
        __stcs(op + 1, w1);
        __stcs(op + 2, w2);
    }
}

// ------------------------------- launch ------------------------------------

extern "C" void kernel_launch(void* const* d_in, const int* in_sizes, int n_in,
                              void* d_out, int out_size) {
    const float* X = (const float*)d_in[0];
    const float* mask = (const float*)d_in[1];
    float* out = (float*)d_out;

    long long BN = in_sizes[1];                       // B*N
    long long B = ((long long)out_size - 24LL * BN) / 75LL;
    if (B < 1) B = 1;
    int N = (int)(BN / B);

    float* outF = out + 24LL * BN;                    // F_ops after h
    float* outC = outF + 72LL * B;                    // center after F_ops

    int S = (N / 4 + 1023) / 1024;                    // 4 segments for N=4096
    if (S < 1) S = 1;
    dim3 rgrid((unsigned)S, (unsigned)B);
    fa_reduce_kernel<<<rgrid, 256>>>(X, mask, N);
    fa_eig_kernel<<<(int)B, 32>>>(outF, outC, (int)B);
    dim3 pgrid((N / 4 + 255) / 256, (unsigned)B);
    fa_project_kernel<<<pgrid, 256>>>(X, mask, out, N);
}

// round 5
// speedup vs baseline: 1.7049x; 1.3602x over previous
#include <cuda_runtime.h>
#include <cuda_bf16.h>

// ---------------------------------------------------------------------------
// FrameAveraging: center/covariance -> 3x3 eigh (LAPACK ssyevd emulation for
// exact sign/order match with jnp.linalg.eigh) -> 8-way sign-flipped
// frame projection.
//
// Outputs (concatenated in d_out): h [B*8,N,3], F_ops [B,8,3,3], center [B,3]
//
// R5 = R3/R4 resubmit (both failed at container level, never ran):
//  - reduce: 512 CTAs, 2 float4-groups per thread, loads front-batched (MLP=8).
//  - project: smem-staged y tile; per-op lane-contiguous float4 stores
//    (16B lane stride -> minimal L1tex wavefronts); signs via sign-bit XOR.
// ---------------------------------------------------------------------------

#define FA_MAXB 1024
__device__ double g_acc[FA_MAXB * 11];   // zero-initialized; restored to 0 each launch
__device__ float g_center[FA_MAXB * 3];
__device__ float g_V[FA_MAXB * 9];       // V[i][j] row-major (column j = eigvec j)

// ----------------------------- LAPACK helpers ------------------------------

__device__ __forceinline__ float f_sign(float a, float b) {
    float aa = fabsf(a);
    return (b >= 0.0f) ? aa : -aa;
}

__device__ __forceinline__ float slapy2f(float x, float y) {
    float ax = fabsf(x), ay = fabsf(y);
    float w = fmaxf(ax, ay), z = fminf(ax, ay);
    if (z == 0.0f) return w;
    float r = z / w;
    return w * sqrtf(1.0f + r * r);
}

// LAPACK >= 3.10 slartg convention: c >= 0, r = sign(f)*hypot, s = g/r.
__device__ __forceinline__ void slartgf(float f, float g, float& c, float& s, float& r) {
    if (g == 0.0f) {
        c = 1.0f; s = 0.0f; r = f;
    } else if (f == 0.0f) {
        c = 0.0f; s = (g >= 0.0f) ? 1.0f : -1.0f; r = fabsf(g);
    } else {
        float d = sqrtf(f * f + g * g);
        c = fabsf(f) / d;
        r = (f >= 0.0f) ? d : -d;
        s = g / r;
    }
}

__device__ void slaev2f(float a, float b, float c,
                        float& rt1, float& rt2, float& cs1, float& sn1) {
    float sm = a + c;
    float df = a - c;
    float adf = fabsf(df);
    float tb = b + b;
    float ab = fabsf(tb);
    float acmx, acmn;
    if (fabsf(a) > fabsf(c)) { acmx = a; acmn = c; } else { acmx = c; acmn = a; }
    float rt;
    if (adf > ab)      { float q = ab / adf;  rt = adf * sqrtf(1.0f + q * q); }
    else if (adf < ab) { float q = adf / ab;  rt = ab  * sqrtf(1.0f + q * q); }
    else               {                      rt = ab  * sqrtf(2.0f); }
    int sgn1;
    if (sm < 0.0f) {
        rt1 = 0.5f * (sm - rt); sgn1 = -1;
        rt2 = (acmx / rt1) * acmn - (b / rt1) * b;
    } else if (sm > 0.0f) {
        rt1 = 0.5f * (sm + rt); sgn1 = 1;
        rt2 = (acmx / rt1) * acmn - (b / rt1) * b;
    } else {
        rt1 = 0.5f * rt; rt2 = -0.5f * rt; sgn1 = 1;
    }
    float cs; int sgn2;
    if (df >= 0.0f) { cs = df + rt; sgn2 = 1; } else { cs = df - rt; sgn2 = -1; }
    float acs = fabsf(cs);
    if (acs > ab) {
        float ct = -tb / cs;
        sn1 = 1.0f / sqrtf(1.0f + ct * ct);
        cs1 = ct * sn1;
    } else {
        if (ab == 0.0f) { cs1 = 1.0f; sn1 = 0.0f; }
        else {
            float tn = -cs / tb;
            cs1 = 1.0f / sqrtf(1.0f + tn * tn);
            sn1 = tn * cs1;
        }
    }
    if (sgn1 == sgn2) { float tn = cs1; cs1 = -sn1; sn1 = tn; }
}

// ssteqr, COMPZ='I', n=3. d[3], e[2], z initialized to identity by the caller.
__device__ void ssteqr3(float d[3], float e[2], float z[3][3]) {
    const float eps = 5.9604645e-08f;          // slamch('E') for f32 = 2^-24
    const float eps2 = eps * eps;
    const float safmin = 1.1754943508222875e-38f;
    const int n = 3;
    const int nmaxit = n * 30;
    int jtot = 0;
    int l1 = 0;

    while (true) {
        if (l1 > n - 1) break;
        if (l1 > 0) e[l1 - 1] = 0.0f;
        int m = n - 1;
        for (int mm = l1; mm <= n - 2; mm++) {
            float tst = fabsf(e[mm]);
            if (tst == 0.0f) { m = mm; break; }
            if (tst <= (sqrtf(fabsf(d[mm])) * sqrtf(fabsf(d[mm + 1]))) * eps) {
                e[mm] = 0.0f; m = mm; break;
            }
        }
        int l = l1, lsv = l, lend = m, lendsv = lend;
        l1 = m + 1;
        if (lend == l) continue;
        if (fabsf(d[lend]) < fabsf(d[l])) { l = lendsv; lend = lsv; }

        if (lend > l) {
            // ---- QL iteration ----
            bool blockdone = false;
            while (!blockdone) {
                int m2 = lend;
                if (l != lend) {
                    for (int mm = l; mm <= lend - 1; mm++) {
                        float tst = e[mm] * e[mm];
                        if (tst <= (eps2 * fabsf(d[mm])) * fabsf(d[mm + 1]) + safmin) {
                            m2 = mm; break;
                        }
                    }
                }
                if (m2 < lend) e[m2] = 0.0f;
                float p = d[l];
                if (m2 == l) {
                    d[l] = p; l++;
                    if (l <= lend) continue;
                    blockdone = true; continue;
                }
                if (m2 == l + 1) {
                    float rt1, rt2, c, s;
                    slaev2f(d[l], e[l], d[l + 1], rt1, rt2, c, s);
                    for (int i = 0; i < 3; i++) {
                        float temp = z[i][l + 1];
                        z[i][l + 1] = c * temp - s * z[i][l];
                        z[i][l]     = s * temp + c * z[i][l];
                    }
                    d[l] = rt1; d[l + 1] = rt2; e[l] = 0.0f;
                    l += 2;
                    if (l <= lend) continue;
                    blockdone = true; continue;
                }
                if (jtot == nmaxit) { blockdone = true; continue; }
                jtot++;
                float g = (d[l + 1] - p) / (2.0f * e[l]);
                float r = slapy2f(g, 1.0f);
                g = d[m2] - p + e[l] / (g + f_sign(r, g));
                float s = 1.0f, c = 1.0f;
                p = 0.0f;
                float csv[2], snv[2];
                for (int i = m2 - 1; i >= l; i--) {
                    float f = s * e[i];
                    float b2 = c * e[i];
                    slartgf(g, f, c, s, r);
                    if (i != m2 - 1) e[i + 1] = r;
                    g = d[i + 1] - p;
                    r = (d[i] - g) * s + 2.0f * c * b2;
                    p = s * r;
                    d[i + 1] = g + p;
                    g = c * r - b2;
                    csv[i] = c; snv[i] = -s;
                }
                for (int j = m2 - 1; j >= l; j--) {        // slasr 'R','V','B'
                    float cj = csv[j], sj = snv[j];
                    for (int i = 0; i < 3; i++) {
                        float temp = z[i][j + 1];
                        z[i][j + 1] = cj * temp - sj * z[i][j];
                        z[i][j]     = sj * temp + cj * z[i][j];
                    }
                }
                d[l] = d[l] - p;
                e[l] = g;
            }
        } else {
            // ---- QR iteration ----
            bool blockdone = false;
            while (!blockdone) {
                int m2 = lend;
                if (l != lend) {
                    for (int mm = l; mm >= lend + 1; mm--) {
                        float tst = e[mm - 1] * e[mm - 1];
                        if (tst <= (eps2 * fabsf(d[mm])) * fabsf(d[mm - 1]) + safmin) {
                            m2 = mm; break;
                        }
                    }
                }
                if (m2 > lend) e[m2 - 1] = 0.0f;
                float p = d[l];
                if (m2 == l) {
                    d[l] = p; l--;
                    if (l >= lend) continue;
                    blockdone = true; continue;
                }
                if (m2 == l - 1) {
                    float rt1, rt2, c, s;
                    slaev2f(d[l - 1], e[l - 1], d[l], rt1, rt2, c, s);
                    for (int i = 0; i < 3; i++) {
                        float temp = z[i][l];
                        z[i][l]     = c * temp - s * z[i][l - 1];
                        z[i][l - 1] = s * temp + c * z[i][l - 1];
                    }
                    d[l - 1] = rt1; d[l] = rt2; e[l - 1] = 0.0f;
                    l -= 2;
                    if (l >= lend) continue;
                    blockdone = true; continue;
                }
                if (jtot == nmaxit) { blockdone = true; continue; }
                jtot++;
                float g = (d[l - 1] - p) / (2.0f * e[l - 1]);
                float r = slapy2f(g, 1.0f);
                g = d[m2] - p + e[l - 1] / (g + f_sign(r, g));
                float s = 1.0f, c = 1.0f;
                p = 0.0f;
                float csv[2], snv[2];
                for (int i = m2; i <= l - 1; i++) {
                    float f = s * e[i];
                    float b2 = c * e[i];
                    slartgf(g, f, c, s, r);
                    if (i != m2) e[i - 1] = r;
                    g = d[i] - p;
                    r = (d[i + 1] - g) * s + 2.0f * c * b2;
                    p = s * r;
                    d[i] = g + p;
                    g = c * r - b2;
                    csv[i] = c; snv[i] = s;
                }
                for (int j = m2; j <= l - 1; j++) {        // slasr 'R','V','F'
                    float cj = csv[j], sj = snv[j];
                    for (int i = 0; i < 3; i++) {
                        float temp = z[i][j + 1];
                        z[i][j + 1] = cj * temp - sj * z[i][j];
                        z[i][j]     = sj * temp + cj * z[i][j];
                    }
                }
                d[l] = d[l] - p;
                e[l - 1] = g;
            }
        }
    }
    // Selection sort ascending, swapping eigenvector columns (LAPACK label 160).
    for (int ii = 1; ii < n; ii++) {
        int i = ii - 1, k = i;
        float p = d[i];
        for (int j = ii; j < n; j++) if (d[j] < p) { k = j; p = d[j]; }
        if (k != i) {
            d[k] = d[i]; d[i] = p;
            for (int r2 = 0; r2 < 3; r2++) {
                float t = z[r2][i]; z[r2][i] = z[r2][k]; z[r2][k] = t;
            }
        }
    }
}

// ----------------------------- Kernel 1: reduce ----------------------------
// grid (S, B), block 256; 2 float4-groups per thread, loads front-batched.

__device__ __forceinline__ float warpRedF(float v) {
#pragma unroll
    for (int o = 16; o > 0; o >>= 1) v += __shfl_down_sync(0xffffffffu, v, o);
    return v;
}

__global__ void __launch_bounds__(256)
fa_reduce_kernel(const float* __restrict__ X,
                 const float* __restrict__ mask, int N) {
    int b = blockIdx.y;
    const float4* Xb = reinterpret_cast<const float4*>(X + (size_t)b * N * 3);
    const float4* Mb = reinterpret_cast<const float4*>(mask + (size_t)b * N);

    float acc[11];
#pragma unroll
    for (int k = 0; k < 11; k++) acc[k] = 0.0f;
    // acc: 0 sm, 1 sm2, 2..4 s1xyz, 5 xx, 6 xy, 7 xz, 8 yy, 9 yz, 10 zz

    int nq = N >> 2;
    int q0 = blockIdx.x * (blockDim.x * 2) + threadIdx.x;
    int q1 = q0 + blockDim.x;

    float4 m40 = {}, a0 = {}, b0 = {}, c0 = {};
    float4 m41 = {}, a1 = {}, b1 = {}, c1 = {};
    bool v0 = q0 < nq, v1 = q1 < nq;
    if (v0) { m40 = Mb[q0]; a0 = Xb[q0 * 3]; b0 = Xb[q0 * 3 + 1]; c0 = Xb[q0 * 3 + 2]; }
    if (v1) { m41 = Mb[q1]; a1 = Xb[q1 * 3]; b1 = Xb[q1 * 3 + 1]; c1 = Xb[q1 * 3 + 2]; }

#pragma unroll
    for (int g = 0; g < 2; g++) {
        float4 fa = g ? a1 : a0, fb = g ? b1 : b0, fc = g ? c1 : c0, m4 = g ? m41 : m40;
        if (!(g ? v1 : v0)) continue;
        float px[4] = {fa.x, fa.w, fb.z, fc.y};
        float py[4] = {fa.y, fb.x, fb.w, fc.z};
        float pz[4] = {fa.z, fb.y, fc.x, fc.w};
        float mm[4] = {m4.x, m4.y, m4.z, m4.w};
#pragma unroll
        for (int k = 0; k < 4; k++) {
            float x = px[k], y = py[k], z = pz[k], m = mm[k];
            acc[0] += m;         acc[1] = fmaf(m, m, acc[1]);
            acc[2] = fmaf(m, x, acc[2]);
            acc[3] = fmaf(m, y, acc[3]);
            acc[4] = fmaf(m, z, acc[4]);
            acc[5] = fmaf(x, x, acc[5]);
            acc[6] = fmaf(x, y, acc[6]);
            acc[7] = fmaf(x, z, acc[7]);
            acc[8] = fmaf(y, y, acc[8]);
            acc[9] = fmaf(y, z, acc[9]);
            acc[10] = fmaf(z, z, acc[10]);
        }
    }

    __shared__ float sred[8][11];
    int lane = threadIdx.x & 31, w = threadIdx.x >> 5;
#pragma unroll
    for (int k = 0; k < 11; k++) {
        float v = warpRedF(acc[k]);
        if (lane == 0) sred[w][k] = v;
    }
    __syncthreads();
    if (threadIdx.x < 11) {
        int nw = blockDim.x >> 5;
        double v = 0.0;
        for (int ww = 0; ww < nw; ww++) v += (double)sred[ww][threadIdx.x];
        atomicAdd(&g_acc[b * 11 + threadIdx.x], v);
    }
}

// ------------------- Kernel 2: finalize + eigh + F_ops ----------------------
// One matrix per CTA (lane 0 only) -> no warp divergence in ssteqr emulation.

__global__ void __launch_bounds__(32)
fa_eig_kernel(float* __restrict__ outF, float* __restrict__ outC, int B) {
    int b = blockIdx.x;
    if (threadIdx.x != 0 || b >= B) return;

    double t[11];
#pragma unroll
    for (int k = 0; k < 11; k++) {
        t[k] = g_acc[b * 11 + k];
        g_acc[b * 11 + k] = 0.0;      // restore zero state for next launch
    }
    double sm = t[0], sm2 = t[1];
    double s1x = t[2], s1y = t[3], s1z = t[4];
    // f32 center exactly as reference computes (f32 divide)
    float cfx = (float)s1x / (float)sm;
    float cfy = (float)s1y / (float)sm;
    float cfz = (float)s1z / (float)sm;
    g_center[b * 3 + 0] = cfx;
    g_center[b * 3 + 1] = cfy;
    g_center[b * 3 + 2] = cfz;
    // C_ij = Sxx_ij - c_i*S1_j - c_j*S1_i + c_i*c_j*Sm2 (double expansion)
    double cx = s1x / sm, cy = s1y / sm, cz = s1z / sm;
    float a11 = (float)(t[5]  - 2.0 * cx * s1x + cx * cx * sm2);
    float a21 = (float)(t[6]  - cx * s1y - cy * s1x + cx * cy * sm2);
    float a31 = (float)(t[7]  - cx * s1z - cz * s1x + cx * cz * sm2);
    float a22 = (float)(t[8]  - 2.0 * cy * s1y + cy * cy * sm2);
    float a32 = (float)(t[9]  - cy * s1z - cz * s1y + cy * cz * sm2);
    float a33 = (float)(t[10] - 2.0 * cz * s1z + cz * cz * sm2);

    // ---- ssytd2 (lower, n=3): one Householder reflector ----
    float d[3], e[2];
    float tau = 0.0f, v2 = 0.0f;
    {
        float alpha = a21;
        float xnorm = fabsf(a31);
        if (xnorm == 0.0f) {
            tau = 0.0f; v2 = 0.0f;
            e[0] = alpha;
            d[0] = a11; d[1] = a22; d[2] = a33;
            e[1] = a32;
        } else {
            float beta = -f_sign(slapy2f(alpha, xnorm), alpha);
            tau = (beta - alpha) / beta;
            v2 = a31 * (1.0f / (alpha - beta));
            e[0] = beta;
            float w1 = tau * (a22 + a32 * v2);
            float w2 = tau * (a32 + a33 * v2);
            float alpha2 = -0.5f * tau * (w1 + w2 * v2);
            w1 += alpha2;
            w2 += alpha2 * v2;
            d[0] = a11;
            d[1] = a22 - 2.0f * w1;
            e[1] = a32 - (v2 * w1 + w2);
            d[2] = a33 - 2.0f * v2 * w2;
        }
    }

    float z[3][3] = {{1.f, 0.f, 0.f}, {0.f, 1.f, 0.f}, {0.f, 0.f, 1.f}};
    ssteqr3(d, e, z);

    // ---- sormtr: V = H1 * Z, H1 = I - tau*u*u^T, u = (0, 1, v2) ----
    float V[3][3];
#pragma unroll
    for (int j = 0; j < 3; j++) {
        float tt = tau * (z[1][j] + v2 * z[2][j]);
        V[0][j] = z[0][j];
        V[1][j] = z[1][j] - tt;
        V[2][j] = z[2][j] - v2 * tt;
    }
#pragma unroll
    for (int i = 0; i < 3; i++)
#pragma unroll
        for (int j = 0; j < 3; j++)
            g_V[b * 9 + i * 3 + j] = V[i][j];

    // F_ops[b,o,i,j] = OPS[o][j] * V[i][j]; OPS[o] = (o&4?+1:-1, o&2?+1:-1, o&1?+1:-1)
    for (int o = 0; o < 8; o++) {
        float sg[3] = {(o & 4) ? 1.f : -1.f, (o & 2) ? 1.f : -1.f, (o & 1) ? 1.f : -1.f};
#pragma unroll
        for (int i = 0; i < 3; i++)
#pragma unroll
            for (int j = 0; j < 3; j++)
                outF[(((size_t)b * 8 + o) * 3 + i) * 3 + j] = sg[j] * V[i][j];
    }
    outC[b * 3 + 0] = cfx;
    outC[b * 3 + 1] = cfy;
    outC[b * 3 + 2] = cfz;
}

// ------------------------- Kernel 3: projection (h) -------------------------
// Block = 256 threads = 1024-point tile. Stage y in smem, then write each op
// row with lane-contiguous float4 stores; signs applied by XOR of sign bit.

__global__ void __launch_bounds__(256)
fa_project_kernel(const float* __restrict__ X,
                  const float* __restrict__ mask,
                  float* __restrict__ outh, int N) {
    int b = blockIdx.y;
    __shared__ float4 sy4[768];          // 1024 points * 3 floats = 3072 f = 768 f4
    __shared__ float sV[9];
    __shared__ float sc[3];
    if (threadIdx.x < 9) sV[threadIdx.x] = g_V[b * 9 + threadIdx.x];
    if (threadIdx.x < 3) sc[threadIdx.x] = g_center[b * 3 + threadIdx.x];
    __syncthreads();

    int tid = threadIdx.x;
    int nq = N >> 2;                      // float4-groups per batch row
    int g = blockIdx.x * blockDim.x + tid;  // this thread's group (4 points)
    bool valid = g < nq;

    const float4* Xb = reinterpret_cast<const float4*>(X + (size_t)b * N * 3);
    const float4* Mb = reinterpret_cast<const float4*>(mask + (size_t)b * N);

    if (valid) {
        float4 fa = Xb[g * 3 + 0];
        float4 fb = Xb[g * 3 + 1];
        float4 fc = Xb[g * 3 + 2];
        float4 m4 = Mb[g];

        float cx = sc[0], cy = sc[1], cz = sc[2];
        float v0 = sV[0], v1 = sV[1], v2 = sV[2];
        float v3 = sV[3], v4 = sV[4], v5 = sV[5];
        float v6 = sV[6], v7 = sV[7], v8 = sV[8];

        float px[4] = {fa.x, fa.w, fb.z, fc.y};
        float py[4] = {fa.y, fb.x, fb.w, fc.z};
        float pz[4] = {fa.z, fb.y, fc.x, fc.w};
        float mm[4] = {m4.x, m4.y, m4.z, m4.w};

        float yv[12];
#pragma unroll
        for (int k = 0; k < 4; k++) {
            float xcx = px[k] - cx * mm[k];
            float xcy = py[k] - cy * mm[k];
            float xcz = pz[k] - cz * mm[k];
            // y_i = sum_j V[j][i] * xc_j (projection onto eigenvector i)
            yv[k * 3 + 0] = v0 * xcx + v3 * xcy + v6 * xcz;
            yv[k * 3 + 1] = v1 * xcx + v4 * xcy + v7 * xcz;
            yv[k * 3 + 2] = v2 * xcx + v5 * xcy + v8 * xcz;
        }
        sy4[tid * 3 + 0] = make_float4(yv[0], yv[1], yv[2],  yv[3]);
        sy4[tid * 3 + 1] = make_float4(yv[4], yv[5], yv[6],  yv[7]);
        sy4[tid * 3 + 2] = make_float4(yv[8], yv[9], yv[10], yv[11]);
    }
    __syncthreads();

    // Tile covers points [tile0, tile0 + 1024); floats [tile0*3, +3072).
    int tile0 = blockIdx.x * blockDim.x * 4;           // first point of tile
    int tile_pts = min(N - tile0, (int)blockDim.x * 4);
    int tile_f4 = (tile_pts * 3) >> 2;                 // float4 count in tile

    // Read this thread's 3 unsigned float4s once; reuse across all 8 ops.
    // Precompute idx%3 per chunk (idx = tid + c*256; 256 % 3 == 1 -> m rotates).
    uint4 u[3];
    int mmod[3];
    int mt = tid % 3;
#pragma unroll
    for (int c = 0; c < 3; c++) {
        int idx = tid + c * blockDim.x;
        mmod[c] = mt;
        mt = (mt == 2) ? 0 : mt + 1;     // (tid + 256) % 3 advances by 1
        if (idx < tile_f4) {
            float4 v = sy4[idx];
            u[c] = make_uint4(__float_as_uint(v.x), __float_as_uint(v.y),
                              __float_as_uint(v.z), __float_as_uint(v.w));
        }
    }

    size_t rowstride = (size_t)N * 3;
    float* obase = outh + ((size_t)b * 8) * rowstride + (size_t)tile0 * 3;

#pragma unroll
    for (int o = 0; o < 8; o++) {
        // component sign masks: +1 -> 0, -1 -> 0x80000000
        unsigned s0 = (o & 4) ? 0u : 0x80000000u;
        unsigned s1 = (o & 2) ? 0u : 0x80000000u;
        unsigned s2 = (o & 1) ? 0u : 0x80000000u;
        // sign-vector for a float4 starting at float offset f (by f mod 3)
        uint4 sm0 = make_uint4(s0, s1, s2, s0);
        uint4 sm1 = make_uint4(s1, s2, s0, s1);
        uint4 sm2 = make_uint4(s2, s0, s1, s2);
        uint4* orow = reinterpret_cast<uint4*>(obase + (size_t)o * rowstride);
#pragma unroll
        for (int c = 0; c < 3; c++) {
            int idx = tid + c * blockDim.x;
            if (idx < tile_f4) {
                int m = mmod[c];
                uint4 sv = (m == 0) ? sm0 : (m == 1) ? sm1 : sm2;
                uint4 w = make_uint4(u[c].x ^ sv.x, u[c].y ^ sv.y,
                                     u[c].z ^ sv.z, u[c].w ^ sv.w);
                __stcs(orow + idx, w);
            }
        }
    }
}

// ------------------------------- launch ------------------------------------

extern "C" void kernel_launch(void* const* d_in, const int* in_sizes, int n_in,
                              void* d_out, int out_size) {
    const float* X = (const float*)d_in[0];
    const float* mask = (const float*)d_in[1];
    float* out = (float*)d_out;

    long long BN = in_sizes[1];                       // B*N
    long long B = ((long long)out_size - 24LL * BN) / 75LL;
    if (B < 1) B = 1;
    int N = (int)(BN / B);

    float* outF = out + 24LL * BN;                    // F_ops after h
    float* outC = outF + 72LL * B;                    // center after F_ops

    int nq = N / 4;
    int S = (nq + 511) / 512;                         // 2 groups per thread
    if (S < 1) S = 1;
    dim3 rgrid((unsigned)S, (unsigned)B);
    fa_reduce_kernel<<<rgrid, 256>>>(X, mask, N);
    fa_eig_kernel<<<(int)B, 32>>>(outF, outC, (int)B);
    dim3 pgrid((unsigned)((nq + 255) / 256), (unsigned)B);
    fa_project_kernel<<<pgrid, 256>>>(X, mask, out, N);
}